// round 7
// baseline (speedup 1.0000x reference)
#include <cuda_runtime.h>

// DCT_26688926778120: grayscale + 8x8 blockwise 2D DCT-II (unnormalized)
// x: (B=8, C=3, T=32, H=256, W=256) fp32 -> out: (B, T, 1024, 8, 8) fp32
//
// One CTA of 256 threads per (b, t, block-row). Thread (j = tid>>3, r = tid&7)
// loads its own block-row (row r, cols [8j,8j+8)) of 3 channels directly from
// GMEM, does grayscale + row DCT in registers, writes Y to smem (stride 257 =
// conflict-free), one barrier, then thread (j, l=r) does the column DCT.
// Per warp+channel the two LDG.128s cover exactly 8 full 128B lines.

#define SM_STRIDE 257  // 257 % 32 == 1 -> conflict-free scalar row/col access

__global__ __launch_bounds__(256) void dct_kernel(
    const float* __restrict__ x, float* __restrict__ out)
{
    // Unnormalized DCT-II matrix D[k][n] = 2*cos(pi*(2n+1)*k/16) as literals
    // -> FFMA with immediate operands, no constant-port pressure.
    #define B1 1.96157056f
    #define B2 1.84775907f
    #define B3 1.66293922f
    #define B4 1.41421356f
    #define B5 1.11114047f
    #define B6 0.76536686f
    #define B7 0.39018064f
    constexpr float D[8][8] = {
        { 2.0f,  2.0f,  2.0f,  2.0f,  2.0f,  2.0f,  2.0f,  2.0f},
        {  B1,    B3,    B5,    B7,   -B7,   -B5,   -B3,   -B1 },
        {  B2,    B6,   -B6,   -B2,   -B2,   -B6,    B6,    B2 },
        {  B3,   -B7,   -B1,   -B5,    B5,    B1,    B7,   -B3 },
        {  B4,   -B4,   -B4,    B4,    B4,   -B4,   -B4,    B4 },
        {  B5,   -B1,    B7,    B3,   -B3,   -B7,    B1,   -B5 },
        {  B6,   -B2,    B2,   -B6,   -B6,    B2,   -B2,    B6 },
        {  B7,   -B5,    B3,   -B1,    B1,   -B3,    B5,   -B7 },
    };

    __shared__ float sm[8 * SM_STRIDE];

    const int cta = blockIdx.x;       // cta = ((b*32 + t)*32 + hb)
    const int hb  = cta & 31;
    const int bt  = cta >> 5;         // b*32 + t
    const int tid = threadIdx.x;
    const int j   = tid >> 3;         // block column 0..31
    const int r   = tid & 7;          // row within block / output col l

    const size_t IMG   = 256u * 256u;       // H*W
    const size_t CSTRD = 32u * IMG;         // T*H*W (channel stride)
    const int b = bt >> 5;
    const int t = bt & 31;

    // Thread's 8-float segment: (b, c, t), row hb*8 + r, cols [8j, 8j+8)
    const float* p0 = x + ((size_t)(b * 3) * 32 + t) * IMG
                        + (size_t)(hb * 8 + r) * 256 + j * 8;
    const float4* v0 = (const float4*)p0;
    const float4* v1 = (const float4*)(p0 + CSTRD);
    const float4* v2 = (const float4*)(p0 + 2 * CSTRD);

    // ---- Front-batched loads: 6 x LDG.128, all independent ----
    float4 a0 = __ldcs(v0);     float4 a1 = __ldcs(v0 + 1);
    float4 b0 = __ldcs(v1);     float4 b1 = __ldcs(v1 + 1);
    float4 c0 = __ldcs(v2);     float4 c1 = __ldcs(v2 + 1);

    // ---- Grayscale in registers ----
    float xr[8];
    xr[0] = fmaf(0.2989f, a0.x, fmaf(0.587f, b0.x, 0.114f * c0.x));
    xr[1] = fmaf(0.2989f, a0.y, fmaf(0.587f, b0.y, 0.114f * c0.y));
    xr[2] = fmaf(0.2989f, a0.z, fmaf(0.587f, b0.z, 0.114f * c0.z));
    xr[3] = fmaf(0.2989f, a0.w, fmaf(0.587f, b0.w, 0.114f * c0.w));
    xr[4] = fmaf(0.2989f, a1.x, fmaf(0.587f, b1.x, 0.114f * c1.x));
    xr[5] = fmaf(0.2989f, a1.y, fmaf(0.587f, b1.y, 0.114f * c1.y));
    xr[6] = fmaf(0.2989f, a1.z, fmaf(0.587f, b1.z, 0.114f * c1.z));
    xr[7] = fmaf(0.2989f, a1.w, fmaf(0.587f, b1.w, 0.114f * c1.w));

    // ---- Row DCT in registers: y = D * xr ----
    float* s = sm + r * SM_STRIDE + j * 8;
    #pragma unroll
    for (int k = 0; k < 8; k++) {
        float acc = 0.0f;
        #pragma unroll
        for (int n = 0; n < 8; n++) acc = fmaf(D[k][n], xr[n], acc);
        s[k] = acc;   // bank = (r + 8(j%4) + k) % 32: all 32 lanes distinct
    }
    __syncthreads();

    // ---- Column DCT: thread (j, l=r) does column l of block j ----
    {
        const int l = r;
        float yc[8], o[8];
        #pragma unroll
        for (int rr = 0; rr < 8; rr++) yc[rr] = sm[rr * SM_STRIDE + j * 8 + l];
        #pragma unroll
        for (int k = 0; k < 8; k++) {
            float acc = 0.0f;
            #pragma unroll
            for (int rr = 0; rr < 8; rr++) acc = fmaf(D[k][rr], yc[rr], acc);
            o[k] = acc;
        }
        // out linear index: (cta*32 + j)*64 + k*8 + l
        float* po = out + ((size_t)cta * 32 + j) * 64 + l;
        #pragma unroll
        for (int k = 0; k < 8; k++) __stcs(po + k * 8, o[k]);  // write-once stream
    }
}

extern "C" void kernel_launch(void* const* d_in, const int* in_sizes, int n_in,
                              void* d_out, int out_size)
{
    const float* x = (const float*)d_in[0];
    float* out = (float*)d_out;
    // Grid: B*T*(H/8) = 8*32*32 = 8192 CTAs, 256 threads each.
    dct_kernel<<<8192, 256>>>(x, out);
}